// round 5
// baseline (speedup 1.0000x reference)
#include <cuda_runtime.h>

// ---------------------------------------------------------------------------
// Device scratch (no allocation allowed). Sized with margin over
// N=4096, E=65536, n=128, D=64.
// ---------------------------------------------------------------------------
#define SCRATCH_ELEMS (1 << 20)
#define MAX_N 8192          // max total nodes
#define MAX_E (1 << 18)     // max edges
#define ROW_CAP 256         // per-row edge bucket capacity

__device__ float g_a[SCRATCH_ELEMS];
__device__ float g_c[SCRATCH_ELEMS];
__device__ int g_count[MAX_N];
__device__ int g_elist[MAX_N * ROW_CAP];
__device__ unsigned char g_flag[MAX_E];

// ---------------------------------------------------------------------------
// Kernel 1: per-node projections (D=64 specialized).
// a[i][d] = sum_k x[i][k]*W[d][k] + b[d] ;  c[i][d] = sum_k x[i][k]*W[d][64+k]
// W [64,128] staged into padded smem (stride 129, conflict-free across d).
// PROJ_BN=8 -> grid = N/8 = 512 blocks: ~3.5 blocks/SM for latency hiding.
// ---------------------------------------------------------------------------
#define PROJ_BN 8

__global__ void proj64_kernel(const float* __restrict__ x,
                              const float* __restrict__ W,
                              const float* __restrict__ bias,
                              int N) {
    __shared__ float ws[64 * 129];
    __shared__ float xs[PROJ_BN][64];

    int tid = threadIdx.x;  // 256

#pragma unroll
    for (int i = tid; i < 64 * 128; i += 256) {
        int r = i >> 7, col = i & 127;
        ws[r * 129 + col] = W[i];
    }

    int base = blockIdx.x * PROJ_BN;
#pragma unroll
    for (int i = tid; i < PROJ_BN * 64; i += 256) {
        int nd = i >> 6, k = i & 63;
        int node = base + nd;
        xs[nd][k] = (node < N) ? x[(size_t)node * 64 + k] : 0.f;
    }
    __syncthreads();

    int d = tid & 63;
    int ty = tid >> 6;  // 0..3 -> nodes ty*2, ty*2+1

    const float* __restrict__ wrow = ws + d * 129;
    float accA[2] = {0.f, 0.f};
    float accC[2] = {0.f, 0.f};

#pragma unroll 8
    for (int k = 0; k < 64; k++) {
        float wA = wrow[k];
        float wC = wrow[64 + k];
#pragma unroll
        for (int u = 0; u < 2; u++) {
            float xv = xs[ty * 2 + u][k];
            accA[u] = fmaf(xv, wA, accA[u]);
            accC[u] = fmaf(xv, wC, accC[u]);
        }
    }

    float bv = bias[d];
#pragma unroll
    for (int u = 0; u < 2; u++) {
        int node = base + ty * 2 + u;
        if (node < N) {
            g_a[(size_t)node * 64 + d] = accA[u] + bv;
            g_c[(size_t)node * 64 + d] = accC[u];
        }
    }
}

// ---------------------------------------------------------------------------
// Kernel 2a: zero per-row counters.
// ---------------------------------------------------------------------------
__global__ void zero_count_kernel(int N) {
    int i = blockIdx.x * blockDim.x + threadIdx.x;
    if (i < N) g_count[i] = 0;
}

// ---------------------------------------------------------------------------
// Kernel 2b: bucket edges by output row (= src node). Overflow -> flag.
// ---------------------------------------------------------------------------
__global__ void place_kernel(const int* __restrict__ edge_index, int E) {
    int e = blockIdx.x * blockDim.x + threadIdx.x;
    if (e >= E) return;
    int src = edge_index[e];
    int slot = atomicAdd(&g_count[src], 1);
    if (slot < ROW_CAP) {
        g_elist[src * ROW_CAP + slot] = e;
        g_flag[e] = 0;
    } else {
        g_flag[e] = 1;
    }
}

// ---------------------------------------------------------------------------
// Kernel 3: fused fill + edge scatter.
// Row gi: srow (smem) accumulates this row's edge attrs via smem atomics,
// then out[gi, j, :] = a[gi] + c[g*n+j] + srow[j]. One coalesced write pass.
// Requires n*D4 <= 2048 float4 (32 KB).
// ---------------------------------------------------------------------------
__global__ void fill_fused_kernel(const int* __restrict__ edge_index,
                                  const float4* __restrict__ edge_attr,
                                  float4* __restrict__ out,
                                  int E, int n, int D4) {
    __shared__ float4 srow[2048];

    int gi = blockIdx.x;
    int g = gi / n;
    int tid = threadIdx.x;
    int nrow4 = n * D4;

    // zero the row buffer
    float4 z = {0.f, 0.f, 0.f, 0.f};
    for (int i = tid; i < nrow4; i += 256) srow[i] = z;

    int cnt = g_count[gi];
    if (cnt > ROW_CAP) cnt = ROW_CAP;
    __syncthreads();

    // scatter this row's edges into smem
    for (int t = tid; t < cnt * D4; t += 256) {
        int e = g_elist[gi * ROW_CAP + t / D4];
        int d4 = t % D4;
        int dst = edge_index[E + e];
        int lj = dst - g * n;
        float4 v = edge_attr[(size_t)e * D4 + d4];
        float* s = reinterpret_cast<float*>(&srow[lj * D4 + d4]);
        atomicAdd(s + 0, v.x);
        atomicAdd(s + 1, v.y);
        atomicAdd(s + 2, v.z);
        atomicAdd(s + 3, v.w);
    }
    __syncthreads();

    const float4* __restrict__ a4 =
        reinterpret_cast<const float4*>(g_a) + (size_t)gi * D4;
    const float4* __restrict__ cbase =
        reinterpret_cast<const float4*>(g_c) + (size_t)g * n * D4;

    int d4 = tid % D4;
    int j0 = tid / D4;
    int jstep = 256 / D4;

    float4 av = a4[d4];
    float4* __restrict__ orow = out + (size_t)gi * n * D4;

    for (int j = j0; j < n; j += jstep) {
        float4 cv = cbase[(size_t)j * D4 + d4];
        float4 sv = srow[j * D4 + d4];
        float4 o;
        o.x = av.x + cv.x + sv.x;
        o.y = av.y + cv.y + sv.y;
        o.z = av.z + cv.z + sv.z;
        o.w = av.w + cv.w + sv.w;
        orow[(size_t)j * D4 + d4] = o;
    }
}

// ---------------------------------------------------------------------------
// Kernel 4: overflow fallback (almost always no-op). Global atomic add for
// edges that did not fit a row bucket.
// ---------------------------------------------------------------------------
__global__ void fallback_kernel(const int* __restrict__ edge_index,
                                const float4* __restrict__ edge_attr,
                                float4* __restrict__ out,
                                int E, int n, int D4) {
    int t = blockIdx.x * blockDim.x + threadIdx.x;
    int e = t / D4;
    if (e >= E) return;
    if (!g_flag[e]) return;
    int d4 = t % D4;
    int src = edge_index[e];
    int dst = edge_index[E + e];
    int g = src / n;
    int lj = dst - g * n;
    float4 v = edge_attr[(size_t)e * D4 + d4];
    atomicAdd(&out[((size_t)src * n + lj) * D4 + d4], v);
}

// ---------------------------------------------------------------------------
// Legacy path (for shapes where a row exceeds 32 KB smem).
// ---------------------------------------------------------------------------
__global__ void fill_kernel(float4* __restrict__ out, int n, int D4) {
    int gi = blockIdx.x;
    int g = gi / n;
    const float4* __restrict__ a4 =
        reinterpret_cast<const float4*>(g_a) + (size_t)gi * D4;
    const float4* __restrict__ cbase =
        reinterpret_cast<const float4*>(g_c) + (size_t)g * n * D4;
    int d4 = threadIdx.x % D4;
    int j0 = threadIdx.x / D4;
    int jstep = blockDim.x / D4;
    float4 av = a4[d4];
    float4* __restrict__ orow = out + (size_t)gi * n * D4;
    for (int j = j0; j < n; j += jstep) {
        float4 cv = cbase[(size_t)j * D4 + d4];
        float4 o;
        o.x = av.x + cv.x;
        o.y = av.y + cv.y;
        o.z = av.z + cv.z;
        o.w = av.w + cv.w;
        orow[(size_t)j * D4 + d4] = o;
    }
}

__global__ void scatter_kernel(const int* __restrict__ edge_index,
                               const float4* __restrict__ edge_attr,
                               const int* __restrict__ batch,
                               float4* __restrict__ out,
                               int E, int n, int D4) {
    int t = blockIdx.x * blockDim.x + threadIdx.x;
    int e = t / D4;
    int d4 = t % D4;
    if (e >= E) return;
    int src = edge_index[e];
    int dst = edge_index[E + e];
    int g = batch[src];
    int lj = dst - g * n;
    float4 v = edge_attr[(size_t)e * D4 + d4];
    atomicAdd(&out[((size_t)src * n + lj) * D4 + d4], v);
}

// ---------------------------------------------------------------------------
extern "C" void kernel_launch(void* const* d_in, const int* in_sizes, int n_in,
                              void* d_out, int out_size) {
    const float* x = (const float*)d_in[0];
    const int* edge_index = (const int*)d_in[1];
    const float* edge_attr = (const float*)d_in[2];
    const int* batch = (const int*)d_in[3];
    // d_in[4] = token_index: unused (it enumerates all (i,j) pairs in order)
    const float* W = (const float*)d_in[5];
    const float* b = (const float*)d_in[6];

    int D = in_sizes[6];     // 64
    int N = in_sizes[3];     // 4096 nodes total
    int E = in_sizes[2] / D; // 65536 edges
    int T = in_sizes[4] / 2; // 524288 pairs
    int n = T / N;           // 128 nodes per graph
    int D4 = D / 4;          // 16 float4 per feature row

    float* out = (float*)d_out;

    bool fused = (n * D4 <= 2048) && (N <= MAX_N) && (E <= MAX_E) && (D == 64);

    // 1. per-node projections
    {
        int grid = (N + PROJ_BN - 1) / PROJ_BN;
        proj64_kernel<<<grid, 256>>>(x, W, b, N);
    }

    if (fused) {
        // 2. bucket edges by output row
        zero_count_kernel<<<(N + 255) / 256, 256>>>(N);
        place_kernel<<<(E + 255) / 256, 256>>>(edge_index, E);

        // 3. fused dense fill + edge scatter (writes the 128 MiB output once)
        fill_fused_kernel<<<N, 256>>>(edge_index, (const float4*)edge_attr,
                                      (float4*)out, E, n, D4);

        // 4. overflow fallback (no-op unless a row had >ROW_CAP edges)
        {
            long long work = (long long)E * D4;
            fallback_kernel<<<(int)((work + 255) / 256), 256>>>(
                edge_index, (const float4*)edge_attr, (float4*)out, E, n, D4);
        }
    } else {
        fill_kernel<<<N, 256>>>((float4*)out, n, D4);
        long long work = (long long)E * D4;
        scatter_kernel<<<(int)((work + 255) / 256), 256>>>(
            edge_index, (const float4*)edge_attr, batch, (float4*)out, E, n, D4);
    }
}

// round 6
// speedup vs baseline: 1.4346x; 1.4346x over previous
#include <cuda_runtime.h>

// ---------------------------------------------------------------------------
// Device scratch. Sized with margin over N=4096, D=64.
// ---------------------------------------------------------------------------
#define SCRATCH_ELEMS (1 << 20)
__device__ float g_a[SCRATCH_ELEMS];
__device__ float g_c[SCRATCH_ELEMS];

// ---------------------------------------------------------------------------
// Kernel 1: per-node projections (D=64 specialized).
// a[i][d] = sum_k x[i][k]*W[d][k] + b[d] ;  c[i][d] = sum_k x[i][k]*W[d][64+k]
// W [64,128] staged into padded smem (stride 129, conflict-free across d).
// PROJ_BN=8 -> grid = N/8 = 512 blocks (~3.5/SM) for latency hiding.
// ---------------------------------------------------------------------------
#define PROJ_BN 8

__global__ void proj64_kernel(const float* __restrict__ x,
                              const float* __restrict__ W,
                              const float* __restrict__ bias,
                              int N) {
    __shared__ float ws[64 * 129];
    __shared__ float xs[PROJ_BN][64];

    int tid = threadIdx.x;  // 256

#pragma unroll
    for (int i = tid; i < 64 * 128; i += 256) {
        int r = i >> 7, col = i & 127;
        ws[r * 129 + col] = W[i];
    }

    int base = blockIdx.x * PROJ_BN;
#pragma unroll
    for (int i = tid; i < PROJ_BN * 64; i += 256) {
        int nd = i >> 6, k = i & 63;
        int node = base + nd;
        xs[nd][k] = (node < N) ? x[(size_t)node * 64 + k] : 0.f;
    }
    __syncthreads();

    int d = tid & 63;
    int ty = tid >> 6;  // 0..3 -> nodes ty*2, ty*2+1

    const float* __restrict__ wrow = ws + d * 129;
    float accA[2] = {0.f, 0.f};
    float accC[2] = {0.f, 0.f};

#pragma unroll 8
    for (int k = 0; k < 64; k++) {
        float wA = wrow[k];
        float wC = wrow[64 + k];
#pragma unroll
        for (int u = 0; u < 2; u++) {
            float xv = xs[ty * 2 + u][k];
            accA[u] = fmaf(xv, wA, accA[u]);
            accC[u] = fmaf(xv, wC, accC[u]);
        }
    }

    float bv = bias[d];
#pragma unroll
    for (int u = 0; u < 2; u++) {
        int node = base + ty * 2 + u;
        if (node < N) {
            g_a[(size_t)node * 64 + d] = accA[u] + bv;
            g_c[(size_t)node * 64 + d] = accC[u];
        }
    }
}

// ---------------------------------------------------------------------------
// Kernel 2: dense fill, R rows per block (all in one graph so the c row-set
// is re-read from L1 on rows 1..R-1 instead of L2).
// out[gi, j, :] = a[gi] + c[g*n + j]
// ---------------------------------------------------------------------------
#define FILL_R 4

__global__ void fill_kernel(float4* __restrict__ out, int n, int D4) {
    int gi0 = blockIdx.x * FILL_R;
    int g = gi0 / n;

    const float4* __restrict__ cbase =
        reinterpret_cast<const float4*>(g_c) + (size_t)g * n * D4;
    const float4* __restrict__ a4 =
        reinterpret_cast<const float4*>(g_a);

    int d4 = threadIdx.x % D4;
    int j0 = threadIdx.x / D4;
    int jstep = blockDim.x / D4;

    // Prefetch this block's a vectors.
    float4 av[FILL_R];
#pragma unroll
    for (int r = 0; r < FILL_R; r++)
        av[r] = a4[(size_t)(gi0 + r) * D4 + d4];

#pragma unroll
    for (int r = 0; r < FILL_R; r++) {
        float4 a = av[r];
        float4* __restrict__ orow = out + (size_t)(gi0 + r) * n * D4;
        for (int j = j0; j < n; j += jstep) {
            float4 cv = cbase[(size_t)j * D4 + d4];  // L1-hit for r >= 1
            float4 o;
            o.x = a.x + cv.x;
            o.y = a.y + cv.y;
            o.z = a.z + cv.z;
            o.w = a.w + cv.w;
            orow[(size_t)j * D4 + d4] = o;
        }
    }
}

// Fallback when n is not divisible by FILL_R.
__global__ void fill1_kernel(float4* __restrict__ out, int n, int D4) {
    int gi = blockIdx.x;
    int g = gi / n;
    const float4* __restrict__ a4 =
        reinterpret_cast<const float4*>(g_a) + (size_t)gi * D4;
    const float4* __restrict__ cbase =
        reinterpret_cast<const float4*>(g_c) + (size_t)g * n * D4;
    int d4 = threadIdx.x % D4;
    int j0 = threadIdx.x / D4;
    int jstep = blockDim.x / D4;
    float4 av = a4[d4];
    float4* __restrict__ orow = out + (size_t)gi * n * D4;
    for (int j = j0; j < n; j += jstep) {
        float4 cv = cbase[(size_t)j * D4 + d4];
        float4 o;
        o.x = av.x + cv.x;
        o.y = av.y + cv.y;
        o.z = av.z + cv.z;
        o.w = av.w + cv.w;
        orow[(size_t)j * D4 + d4] = o;
    }
}

// ---------------------------------------------------------------------------
// Kernel 3: edge scatter-add. out[src, dst - g*n, :] += attr[e, :]
// (g*n + li == src for equal-sized graphs; g = src / n.)
// 128-bit atomicAdd (native REDG.128 on sm_90+). Indices are int32.
// ---------------------------------------------------------------------------
__global__ void scatter_kernel(const int* __restrict__ edge_index,
                               const float4* __restrict__ edge_attr,
                               float4* __restrict__ out,
                               int E, int n, int D4) {
    int t = blockIdx.x * blockDim.x + threadIdx.x;
    int e = t / D4;
    int d4 = t % D4;
    if (e >= E) return;

    int src = edge_index[e];
    int dst = edge_index[E + e];
    int g = src / n;
    int lj = dst - g * n;

    float4 v = edge_attr[(size_t)e * D4 + d4];
    atomicAdd(&out[((size_t)src * n + lj) * D4 + d4], v);
}

// ---------------------------------------------------------------------------
extern "C" void kernel_launch(void* const* d_in, const int* in_sizes, int n_in,
                              void* d_out, int out_size) {
    const float* x = (const float*)d_in[0];
    const int* edge_index = (const int*)d_in[1];
    const float* edge_attr = (const float*)d_in[2];
    // d_in[3] = batch: implied by src / n for equal-sized graphs
    // d_in[4] = token_index: unused (it enumerates all (i,j) pairs in order)
    const float* W = (const float*)d_in[5];
    const float* b = (const float*)d_in[6];

    int D = in_sizes[6];     // 64
    int N = in_sizes[3];     // 4096 nodes total
    int E = in_sizes[2] / D; // 65536 edges
    int T = in_sizes[4] / 2; // 524288 pairs
    int n = T / N;           // 128 nodes per graph
    int D4 = D / 4;          // 16 float4 per feature row

    float* out = (float*)d_out;

    // 1. per-node projections
    {
        int grid = (N + PROJ_BN - 1) / PROJ_BN;
        proj64_kernel<<<grid, 256>>>(x, W, b, N);
    }

    // 2. dense broadcast fill (writes the whole 128 MiB output once)
    if (n % FILL_R == 0)
        fill_kernel<<<N / FILL_R, 256>>>((float4*)out, n, D4);
    else
        fill1_kernel<<<N, 256>>>((float4*)out, n, D4);

    // 3. edge feature scatter-add
    {
        long long work = (long long)E * D4;
        scatter_kernel<<<(int)((work + 255) / 256), 256>>>(
            edge_index, (const float4*)edge_attr, (float4*)out, E, n, D4);
    }
}